// round 8
// baseline (speedup 1.0000x reference)
#include <cuda_runtime.h>
#include <math.h>
#include <stdint.h>

#define NN_MAX 100000
#define ADIM   1000

// ------------------------- scratch (no runtime alloc) -----------------------
__device__ float g_h   [(size_t)NN_MAX*128];
__device__ float g_agg [(size_t)NN_MAX*128];
__device__ float g_h1  [(size_t)NN_MAX*256];
__device__ float g_h2  [(size_t)NN_MAX*256];
__device__ float g_deg [NN_MAX];
__device__ float g_dinv[NN_MAX];
__device__ float g_conc[NN_MAX];
__device__ float g_lg  [NN_MAX];

// ------------------------- threefry2x32 (JAX-exact) -------------------------
struct K2 { unsigned a, b; };

__device__ __forceinline__ void tf_round(unsigned &x0, unsigned &x1, int r) {
    x0 += x1;
    x1 = (x1 << r) | (x1 >> (32 - r));
    x1 ^= x0;
}
__device__ __forceinline__ K2 tf_block(unsigned k0, unsigned k1, unsigned x0, unsigned x1) {
    unsigned k2 = k0 ^ k1 ^ 0x1BD11BDAu;
    x0 += k0; x1 += k1;
    tf_round(x0,x1,13); tf_round(x0,x1,15); tf_round(x0,x1,26); tf_round(x0,x1,6);
    x0 += k1; x1 += k2 + 1u;
    tf_round(x0,x1,17); tf_round(x0,x1,29); tf_round(x0,x1,16); tf_round(x0,x1,24);
    x0 += k2; x1 += k0 + 2u;
    tf_round(x0,x1,13); tf_round(x0,x1,15); tf_round(x0,x1,26); tf_round(x0,x1,6);
    x0 += k0; x1 += k1 + 3u;
    tf_round(x0,x1,17); tf_round(x0,x1,29); tf_round(x0,x1,16); tf_round(x0,x1,24);
    x0 += k1; x1 += k2 + 4u;
    tf_round(x0,x1,13); tf_round(x0,x1,15); tf_round(x0,x1,26); tf_round(x0,x1,6);
    x0 += k2; x1 += k0 + 5u;
    K2 r; r.a = x0; r.b = x1; return r;
}
__device__ __forceinline__ unsigned rbits(K2 k) {
    K2 r = tf_block(k.a, k.b, 0u, 0u);
    return r.a ^ r.b;
}
__device__ __forceinline__ void split2(K2 k, K2 &o0, K2 &o1) {
    o0 = tf_block(k.a, k.b, 0u, 0u);
    o1 = tf_block(k.a, k.b, 0u, 1u);
}
__device__ __forceinline__ void split3(K2 k, K2 &o0, K2 &o1, K2 &o2) {
    o0 = tf_block(k.a, k.b, 0u, 0u);
    o1 = tf_block(k.a, k.b, 0u, 1u);
    o2 = tf_block(k.a, k.b, 0u, 2u);
}
__device__ __forceinline__ K2 split_big(K2 k, unsigned i) {
    return tf_block(k.a, k.b, 0u, i);
}
__device__ __forceinline__ float u01(K2 k) {
    unsigned bits = rbits(k);
    return __uint_as_float((bits >> 9) | 0x3f800000u) - 1.0f;
}
__device__ __forceinline__ float erfinv_xla(float x) {
    float xx = __fmul_rn(x, x);
    float w = (float)(-log1p(-(double)xx));
    float p;
    if (w < 5.0f) {
        w = __fsub_rn(w, 2.5f);
        p = 2.81022636e-08f;
        p = fmaf(p, w, 3.43273939e-07f);
        p = fmaf(p, w, -3.5233877e-06f);
        p = fmaf(p, w, -4.39150654e-06f);
        p = fmaf(p, w, 0.00021858087f);
        p = fmaf(p, w, -0.00125372503f);
        p = fmaf(p, w, -0.00417768164f);
        p = fmaf(p, w, 0.246640727f);
        p = fmaf(p, w, 1.50140941f);
    } else {
        w = __fsub_rn(__fsqrt_rn(w), 3.0f);
        p = -0.000200214257f;
        p = fmaf(p, w, 0.000100950558f);
        p = fmaf(p, w, 0.00134934322f);
        p = fmaf(p, w, -0.00367342844f);
        p = fmaf(p, w, 0.00573950773f);
        p = fmaf(p, w, -0.0076224613f);
        p = fmaf(p, w, 0.00943887047f);
        p = fmaf(p, w, 1.00167406f);
        p = fmaf(p, w, 2.83297682f);
    }
    return __fmul_rn(p, x);
}
__device__ __forceinline__ float nrm(K2 k) {
    float f = u01(k);
    const float lo = __uint_as_float(0xBF7FFFFFu);
    float v = __fadd_rn(__fmul_rn(f, 2.0f), lo);
    v = fmaxf(lo, v);
    return __fmul_rn(__uint_as_float(0x3FB504F3u), erfinv_xla(v));
}

// ------------------------- degree / norm ------------------------------------
__global__ void k_deg_init(int n) {
    int i = blockIdx.x * blockDim.x + threadIdx.x;
    if (i < n) g_deg[i] = 1.0f;
}
__global__ void k_deg_count(const int* __restrict__ dst, int E) {
    int e = blockIdx.x * blockDim.x + threadIdx.x;
    if (e < E) atomicAdd(&g_deg[dst[e]], 1.0f);
}
__global__ void k_dinv(int n) {
    int i = blockIdx.x * blockDim.x + threadIdx.x;
    if (i < n) g_dinv[i] = (float)(1.0 / sqrt((double)g_deg[i]));
}
__global__ void k_self(int n4) {
    int idx = blockIdx.x * blockDim.x + threadIdx.x;
    if (idx >= n4) return;
    int node = idx >> 5;
    float di = g_dinv[node];
    float n2 = __fmul_rn(di, di);
    float4 v = ((const float4*)g_h)[idx];
    float4 o;
    o.x = __fmul_rn(v.x, n2); o.y = __fmul_rn(v.y, n2);
    o.z = __fmul_rn(v.z, n2); o.w = __fmul_rn(v.w, n2);
    ((float4*)g_agg)[idx] = o;
}
__global__ void k_scatter(const int* __restrict__ src, const int* __restrict__ dst, int E) {
    int e = blockIdx.x * 8 + (threadIdx.x >> 5);
    if (e >= E) return;
    int lane = threadIdx.x & 31;
    int s = __ldg(&src[e]);
    int d = __ldg(&dst[e]);
    float norm = __fmul_rn(g_dinv[s], g_dinv[d]);
    float4 v = *(const float4*)(g_h + (size_t)s * 128 + lane * 4);
    float* out = g_agg + (size_t)d * 128 + lane * 4;
    float m0 = __fmul_rn(v.x, norm);
    float m1 = __fmul_rn(v.y, norm);
    float m2 = __fmul_rn(v.z, norm);
    float m3 = __fmul_rn(v.w, norm);
    asm volatile("red.global.add.v4.f32 [%0], {%1,%2,%3,%4};"
                 :: "l"(out), "f"(m0), "f"(m1), "f"(m2), "f"(m3) : "memory");
}
__global__ void k_prep(const float* __restrict__ x, const float* __restrict__ bc, int n4) {
    int idx = blockIdx.x * blockDim.x + threadIdx.x;
    if (idx >= n4) return;
    int c4 = (idx & 31);
    float4 g = ((const float4*)g_agg)[idx];
    float4 xv = ((const float4*)x)[idx];
    float4 b = ((const float4*)bc)[c4];
    float4 o;
    o.x = __fadd_rn(fmaxf(__fadd_rn(g.x, b.x), 0.f), xv.x);
    o.y = __fadd_rn(fmaxf(__fadd_rn(g.y, b.y), 0.f), xv.y);
    o.z = __fadd_rn(fmaxf(__fadd_rn(g.z, b.z), 0.f), xv.z);
    o.w = __fadd_rn(fmaxf(__fadd_rn(g.w, b.w), 0.f), xv.w);
    ((float4*)g_h)[idx] = o;
}

// ------------------------- GEMM: cp.async 3-stage SGEMM ---------------------
// 128x128 block tile, 256 threads, 8x8 thread tile (split 4+4 cols), KB=16.
// A in smem row-major pitch 20 floats (16B-aligned rows), W row-major 16x128.
// EPI=0: C = A@W.  EPI=1: C = leaky(A@W + bout).
#define KB     16
#define APITCH 20
#define A_STG  (128 * APITCH * 4)          // 10240 B
#define W_STG  (KB * 128 * 4)              // 8192 B
#define STG    (A_STG + W_STG)
#define TG_SMEM (3 * STG)                  // 55296 B

__device__ __forceinline__ void cp16(uint32_t dst, const void* src, int size) {
    asm volatile("cp.async.cg.shared.global [%0], [%1], 16, %2;"
                 :: "r"(dst), "l"(src), "r"(size) : "memory");
}

template<int K, int LDW, int LDA, int LDC, int EPI>
__global__ void __launch_bounds__(256) k_gemm(const float* __restrict__ A,
                                              const float* __restrict__ W,
                                              const float* __restrict__ bout,
                                              float* __restrict__ Cout, int N) {
    extern __shared__ char smem[];
    uint32_t sbase;
    asm("{ .reg .u64 t; cvta.to.shared.u64 t, %1; cvt.u32.u64 %0, t; }"
        : "=r"(sbase) : "l"(smem));

    const int t    = threadIdx.x;
    const int row0 = blockIdx.x * 128;
    const int c0   = blockIdx.y * 128;
    const int S    = K / KB;

    // loader indices: A — 2 float4/thread (512 total), W — 2 float4/thread
    const int a_r0 = t >> 2;                 // f4id t     -> row t>>2
    const int a_k0 = (t & 3) * 4;            // k-offset within 16
    const int a_r1 = (t + 256) >> 2;
    const int a_k1 = ((t + 256) & 3) * 4;
    const int w_k0 = t >> 5;                 // k-row 0..7
    const int w_c0 = (t & 31) * 4;
    const int w_k1 = (t + 256) >> 5;         // k-row 8..15
    const int w_c1 = ((t + 256) & 31) * 4;

    // compute indices
    const int tx = t & 15;
    const int ty = t >> 4;
    const int cx = tx * 4;                   // cols cx..cx+3 and cx+64..cx+67
    const int r0 = ty * 8;

    float acc[8][8];
#pragma unroll
    for (int j = 0; j < 8; j++)
#pragma unroll
        for (int q = 0; q < 8; q++) acc[j][q] = 0.f;

    const int sz0 = (row0 + a_r0 < N) ? 16 : 0;
    const int sz1 = (row0 + a_r1 < N) ? 16 : 0;
    const float* Ap0 = A + (size_t)(row0 + a_r0) * LDA + a_k0;
    const float* Ap1 = A + (size_t)(row0 + a_r1) * LDA + a_k1;
    const float* Wp0 = W + (size_t)w_k0 * LDW + c0 + w_c0;
    const float* Wp1 = W + (size_t)w_k1 * LDW + c0 + w_c1;
    const uint32_t dA0 = (uint32_t)(a_r0 * APITCH + a_k0) * 4;
    const uint32_t dA1 = (uint32_t)(a_r1 * APITCH + a_k1) * 4;
    const uint32_t dW0 = (uint32_t)(w_k0 * 128 + w_c0) * 4;
    const uint32_t dW1 = (uint32_t)(w_k1 * 128 + w_c1) * 4;

    // issue loads for slice ks into stage stg
    auto load_stage = [&](int stg, int ks) {
        const int k0 = ks * KB;
        const uint32_t sb = sbase + stg * STG;
        cp16(sb + dA0, Ap0 + k0, sz0);
        cp16(sb + dA1, Ap1 + k0, sz1);
        cp16(sb + A_STG + dW0, Wp0 + (size_t)k0 * LDW, 16);
        cp16(sb + A_STG + dW1, Wp1 + (size_t)k0 * LDW, 16);
    };

    load_stage(0, 0);
    asm volatile("cp.async.commit_group;" ::: "memory");
    if (S > 1) load_stage(1, 1);
    asm volatile("cp.async.commit_group;" ::: "memory");

    for (int s = 0; s < S; s++) {
        asm volatile("cp.async.wait_group 1;" ::: "memory");
        __syncthreads();
        // issue next-next slice (overlaps with compute below)
        if (s + 2 < S) load_stage((s + 2) % 3, s + 2);
        asm volatile("cp.async.commit_group;" ::: "memory");

        const int buf = s % 3;
        const float* sA = (const float*)(smem + buf * STG);
        const float* sW = (const float*)(smem + buf * STG + A_STG);
#pragma unroll
        for (int k = 0; k < KB; k++) {
            float4 w0 = *(const float4*)(sW + k * 128 + cx);
            float4 w1 = *(const float4*)(sW + k * 128 + cx + 64);
            float a[8];
#pragma unroll
            for (int j = 0; j < 8; j++) a[j] = sA[(r0 + j) * APITCH + k];
#pragma unroll
            for (int j = 0; j < 8; j++) {
                acc[j][0] = fmaf(a[j], w0.x, acc[j][0]);
                acc[j][1] = fmaf(a[j], w0.y, acc[j][1]);
                acc[j][2] = fmaf(a[j], w0.z, acc[j][2]);
                acc[j][3] = fmaf(a[j], w0.w, acc[j][3]);
                acc[j][4] = fmaf(a[j], w1.x, acc[j][4]);
                acc[j][5] = fmaf(a[j], w1.y, acc[j][5]);
                acc[j][6] = fmaf(a[j], w1.z, acc[j][6]);
                acc[j][7] = fmaf(a[j], w1.w, acc[j][7]);
            }
        }
        __syncthreads();
    }

    float4 b0 = make_float4(0.f, 0.f, 0.f, 0.f);
    float4 b1v = b0;
    if (EPI) {
        b0  = *(const float4*)(bout + c0 + cx);
        b1v = *(const float4*)(bout + c0 + cx + 64);
    }
#pragma unroll
    for (int j = 0; j < 8; j++) {
        int row = row0 + r0 + j;
        if (row >= N) continue;
        float4 o0 = make_float4(acc[j][0], acc[j][1], acc[j][2], acc[j][3]);
        float4 o1 = make_float4(acc[j][4], acc[j][5], acc[j][6], acc[j][7]);
        if (EPI) {
            o0.x = __fadd_rn(o0.x, b0.x);  o0.x = (o0.x >= 0.f) ? o0.x : __fmul_rn(0.01f, o0.x);
            o0.y = __fadd_rn(o0.y, b0.y);  o0.y = (o0.y >= 0.f) ? o0.y : __fmul_rn(0.01f, o0.y);
            o0.z = __fadd_rn(o0.z, b0.z);  o0.z = (o0.z >= 0.f) ? o0.z : __fmul_rn(0.01f, o0.z);
            o0.w = __fadd_rn(o0.w, b0.w);  o0.w = (o0.w >= 0.f) ? o0.w : __fmul_rn(0.01f, o0.w);
            o1.x = __fadd_rn(o1.x, b1v.x); o1.x = (o1.x >= 0.f) ? o1.x : __fmul_rn(0.01f, o1.x);
            o1.y = __fadd_rn(o1.y, b1v.y); o1.y = (o1.y >= 0.f) ? o1.y : __fmul_rn(0.01f, o1.y);
            o1.z = __fadd_rn(o1.z, b1v.z); o1.z = (o1.z >= 0.f) ? o1.z : __fmul_rn(0.01f, o1.z);
            o1.w = __fadd_rn(o1.w, b1v.w); o1.w = (o1.w >= 0.f) ? o1.w : __fmul_rn(0.01f, o1.w);
        }
        *(float4*)(Cout + (size_t)row * LDC + c0 + cx)      = o0;
        *(float4*)(Cout + (size_t)row * LDC + c0 + cx + 64) = o1;
    }
}

// conc = softplus(h2 @ W3 + b3) + 1e-20   (warp per row)
__global__ void k_conc(const float* __restrict__ W3, const float* __restrict__ b3, int N) {
    int row = blockIdx.x * 8 + (threadIdx.x >> 5);
    if (row >= N) return;
    int lane = threadIdx.x & 31;
    const float4* hr = (const float4*)(g_h2 + (size_t)row * 256);
    const float4* w4 = (const float4*)W3;
    float s = 0.f;
#pragma unroll
    for (int j = lane; j < 64; j += 32) {
        float4 a = hr[j], w = w4[j];
        s = fmaf(a.x, w.x, s); s = fmaf(a.y, w.y, s);
        s = fmaf(a.z, w.z, s); s = fmaf(a.w, w.w, s);
    }
#pragma unroll
    for (int o = 16; o; o >>= 1) s += __shfl_xor_sync(0xFFFFFFFFu, s, o);
    if (lane == 0) {
        float z = __fadd_rn(s, b3[0]);
        double sp = fmax((double)z, 0.0) + log1p(exp(-fabs((double)z)));
        g_conc[row] = __fadd_rn((float)sp, 1e-20f);
    }
}

// ------------------------- loggamma sampler (jax _gamma_one) -----------------
__global__ void k_sample(int N) {
    int i = blockIdx.x * blockDim.x + threadIdx.x;
    if (i >= N) return;
    float alpha = g_conc[i];
    K2 key = split_big(K2{0u, 42u}, (unsigned)i);

    bool boost = (alpha >= 1.0f);
    float alpha_b = boost ? alpha : __fadd_rn(alpha, 1.0f);
    const float third = 0.3333333433f;
    float d = __fsub_rn(alpha_b, third);
    float c = __fdiv_rn(third, __fsqrt_rn(d));

    K2 k0, sub;
    split2(key, k0, sub);
    key = k0;
    float u_boost = u01(sub);

    float V;
    for (;;) {
        K2 nk, xk, uk;
        split3(key, nk, xk, uk);
        key = nk;
        float x, v;
        K2 kk = xk;
        do {
            K2 a, b;
            split2(kk, a, b);
            kk = a;
            x = nrm(b);
            v = __fadd_rn(1.0f, __fmul_rn(c, x));
        } while (v <= 0.0f);
        float X = __fmul_rn(x, x);
        V = __fmul_rn(__fmul_rn(v, v), v);
        float U = u01(uk);
        float sq = __fsub_rn(1.0f, __fmul_rn(0.0331f, __fmul_rn(X, X)));
        if (U < sq) break;
        float logU = (float)log((double)U);
        float logV = (float)log((double)V);
        float rhs = __fadd_rn(__fmul_rn(X, 0.5f),
                              __fmul_rn(d, __fadd_rn(__fsub_rn(1.0f, V), logV)));
        if (logU < rhs) break;
    }
    float log_sample = __fadd_rn((float)log((double)d), (float)log((double)V));
    float lg;
    if (boost) lg = log_sample;
    else {
        float lb = __fmul_rn((float)log1p(-(double)u_boost), __fdiv_rn(1.0f, alpha));
        lg = __fadd_rn(log_sample, lb);
    }
    g_lg[i] = lg;
}

// ------------------------- per-row finish: softmax + log_prob ----------------
__global__ void k_row(float* __restrict__ out, int N, int writeLP) {
    int b = blockIdx.x;
    int t = threadIdx.x;
    __shared__ float  rf[256];
    __shared__ double rd[256];
    const float* lg = g_lg   + (size_t)b * ADIM;
    const float* cc = g_conc + (size_t)b * ADIM;

    float m = -1e30f;
    for (int j = t; j < ADIM; j += 256) m = fmaxf(m, lg[j]);
    rf[t] = m; __syncthreads();
    for (int s = 128; s; s >>= 1) { if (t < s) rf[t] = fmaxf(rf[t], rf[t + s]); __syncthreads(); }
    m = rf[0]; __syncthreads();

    float se = 0.f;
    for (int j = t; j < ADIM; j += 256)
        se = __fadd_rn(se, (float)exp((double)__fsub_rn(lg[j], m)));
    rf[t] = se; __syncthreads();
    for (int s = 128; s; s >>= 1) { if (t < s) rf[t] = __fadd_rn(rf[t], rf[t + s]); __syncthreads(); }
    float lse = __fadd_rn((float)log((double)rf[0]), m);
    __syncthreads();

    double t1 = 0.0, t3 = 0.0, sc = 0.0;
    for (int j = t; j < ADIM; j += 256) {
        float af = (float)exp((double)__fsub_rn(lg[j], lse));
        out[(size_t)b * ADIM + j] = af;
        float cj = cc[j];
        t1 += (double)__fsub_rn(cj, 1.0f) * log((double)af);
        t3 += (double)lgammaf(cj);
        sc += (double)cj;
    }
    rd[t] = t1; __syncthreads();
    for (int s = 128; s; s >>= 1) { if (t < s) rd[t] += rd[t + s]; __syncthreads(); }
    t1 = rd[0]; __syncthreads();
    rd[t] = t3; __syncthreads();
    for (int s = 128; s; s >>= 1) { if (t < s) rd[t] += rd[t + s]; __syncthreads(); }
    t3 = rd[0]; __syncthreads();
    rd[t] = sc; __syncthreads();
    for (int s = 128; s; s >>= 1) { if (t < s) rd[t] += rd[t + s]; __syncthreads(); }
    sc = rd[0];

    if (t == 0 && writeLP) {
        float scf = (float)sc;
        double lp = t1 + lgamma((double)scf) - t3;
        out[(size_t)N + b] = (float)lp;
    }
}

// ------------------------- launch -------------------------------------------
extern "C" void kernel_launch(void* const* d_in, const int* in_sizes, int n_in,
                              void* d_out, int out_size) {
    const float* x      = (const float*)d_in[0];
    const float* W_conv = (const float*)d_in[1];
    const float* b_conv = (const float*)d_in[2];
    const float* W1     = (const float*)d_in[3];
    const float* b1     = (const float*)d_in[4];
    const float* W2     = (const float*)d_in[5];
    const float* b2     = (const float*)d_in[6];
    const float* W3     = (const float*)d_in[7];
    const float* b3     = (const float*)d_in[8];
    const int*   ei     = (const int*)d_in[9];
    float* out = (float*)d_out;

    int N = in_sizes[0] / 128;
    int E = in_sizes[9] / 2;
    int B = N / ADIM;
    const int* src = ei;
    const int* dst = ei + E;

    cudaFuncSetAttribute(k_gemm<128,128,128,128,0>, cudaFuncAttributeMaxDynamicSharedMemorySize, TG_SMEM);
    cudaFuncSetAttribute(k_gemm<128,256,128,256,1>, cudaFuncAttributeMaxDynamicSharedMemorySize, TG_SMEM);
    cudaFuncSetAttribute(k_gemm<256,256,256,256,1>, cudaFuncAttributeMaxDynamicSharedMemorySize, TG_SMEM);

    k_deg_init<<<(N + 255) / 256, 256>>>(N);
    k_deg_count<<<(E + 255) / 256, 256>>>(dst, E);
    k_dinv<<<(N + 255) / 256, 256>>>(N);

    float* gh = nullptr; float* gh1 = nullptr; float* gh2 = nullptr;
    cudaGetSymbolAddress((void**)&gh,  g_h);
    cudaGetSymbolAddress((void**)&gh1, g_h1);
    cudaGetSymbolAddress((void**)&gh2, g_h2);

    int RB = (N + 127) / 128;
    dim3 g0(RB, 1), g1(RB, 2);

    // h = x @ Wc
    k_gemm<128,128,128,128,0><<<g0, 256, TG_SMEM>>>(x, W_conv, nullptr, gh, N);
    k_self<<<(N * 32 + 255) / 256, 256>>>(N * 32);
    k_scatter<<<(E + 7) / 8, 256>>>(src, dst, E);
    // g_h <- relu(agg + b_conv) + x
    k_prep<<<(N * 32 + 255) / 256, 256>>>(x, b_conv, N * 32);
    // h1 = leaky(g_h @ W1 + b1)
    k_gemm<128,256,128,256,1><<<g1, 256, TG_SMEM>>>(gh, W1, b1, gh1, N);
    // h2 = leaky(h1 @ W2 + b2)
    k_gemm<256,256,256,256,1><<<g1, 256, TG_SMEM>>>(gh1, W2, b2, gh2, N);
    k_conc<<<(N + 7) / 8, 256>>>(W3, b3, N);
    k_sample<<<(N + 127) / 128, 128>>>(N);
    int writeLP = (out_size >= N + B) ? 1 : 0;
    k_row<<<B, 256>>>(out, N, writeLP);
}

// round 9
// speedup vs baseline: 1.0706x; 1.0706x over previous
#include <cuda_runtime.h>
#include <math.h>
#include <stdint.h>

#define NN_MAX 100000
#define ADIM   1000

// ------------------------- scratch (no runtime alloc) -----------------------
__device__ float g_h   [(size_t)NN_MAX*128];
__device__ float g_agg [(size_t)NN_MAX*128];
__device__ float g_h1  [(size_t)NN_MAX*256];
__device__ float g_h2  [(size_t)NN_MAX*256];
__device__ float g_deg [NN_MAX];
__device__ float g_dinv[NN_MAX];
__device__ float g_conc[NN_MAX];
__device__ float g_lg  [NN_MAX];

// ------------------------- threefry2x32 (JAX-exact) -------------------------
struct K2 { unsigned a, b; };

__device__ __forceinline__ void tf_round(unsigned &x0, unsigned &x1, int r) {
    x0 += x1;
    x1 = (x1 << r) | (x1 >> (32 - r));
    x1 ^= x0;
}
__device__ __forceinline__ K2 tf_block(unsigned k0, unsigned k1, unsigned x0, unsigned x1) {
    unsigned k2 = k0 ^ k1 ^ 0x1BD11BDAu;
    x0 += k0; x1 += k1;
    tf_round(x0,x1,13); tf_round(x0,x1,15); tf_round(x0,x1,26); tf_round(x0,x1,6);
    x0 += k1; x1 += k2 + 1u;
    tf_round(x0,x1,17); tf_round(x0,x1,29); tf_round(x0,x1,16); tf_round(x0,x1,24);
    x0 += k2; x1 += k0 + 2u;
    tf_round(x0,x1,13); tf_round(x0,x1,15); tf_round(x0,x1,26); tf_round(x0,x1,6);
    x0 += k0; x1 += k1 + 3u;
    tf_round(x0,x1,17); tf_round(x0,x1,29); tf_round(x0,x1,16); tf_round(x0,x1,24);
    x0 += k1; x1 += k2 + 4u;
    tf_round(x0,x1,13); tf_round(x0,x1,15); tf_round(x0,x1,26); tf_round(x0,x1,6);
    x0 += k2; x1 += k0 + 5u;
    K2 r; r.a = x0; r.b = x1; return r;
}
__device__ __forceinline__ unsigned rbits(K2 k) {
    K2 r = tf_block(k.a, k.b, 0u, 0u);
    return r.a ^ r.b;
}
__device__ __forceinline__ void split2(K2 k, K2 &o0, K2 &o1) {
    o0 = tf_block(k.a, k.b, 0u, 0u);
    o1 = tf_block(k.a, k.b, 0u, 1u);
}
__device__ __forceinline__ void split3(K2 k, K2 &o0, K2 &o1, K2 &o2) {
    o0 = tf_block(k.a, k.b, 0u, 0u);
    o1 = tf_block(k.a, k.b, 0u, 1u);
    o2 = tf_block(k.a, k.b, 0u, 2u);
}
__device__ __forceinline__ K2 split_big(K2 k, unsigned i) {
    return tf_block(k.a, k.b, 0u, i);
}
__device__ __forceinline__ float u01(K2 k) {
    unsigned bits = rbits(k);
    return __uint_as_float((bits >> 9) | 0x3f800000u) - 1.0f;
}
__device__ __forceinline__ float erfinv_xla(float x) {
    float xx = __fmul_rn(x, x);
    float w = (float)(-log1p(-(double)xx));
    float p;
    if (w < 5.0f) {
        w = __fsub_rn(w, 2.5f);
        p = 2.81022636e-08f;
        p = fmaf(p, w, 3.43273939e-07f);
        p = fmaf(p, w, -3.5233877e-06f);
        p = fmaf(p, w, -4.39150654e-06f);
        p = fmaf(p, w, 0.00021858087f);
        p = fmaf(p, w, -0.00125372503f);
        p = fmaf(p, w, -0.00417768164f);
        p = fmaf(p, w, 0.246640727f);
        p = fmaf(p, w, 1.50140941f);
    } else {
        w = __fsub_rn(__fsqrt_rn(w), 3.0f);
        p = -0.000200214257f;
        p = fmaf(p, w, 0.000100950558f);
        p = fmaf(p, w, 0.00134934322f);
        p = fmaf(p, w, -0.00367342844f);
        p = fmaf(p, w, 0.00573950773f);
        p = fmaf(p, w, -0.0076224613f);
        p = fmaf(p, w, 0.00943887047f);
        p = fmaf(p, w, 1.00167406f);
        p = fmaf(p, w, 2.83297682f);
    }
    return __fmul_rn(p, x);
}
__device__ __forceinline__ float nrm(K2 k) {
    float f = u01(k);
    const float lo = __uint_as_float(0xBF7FFFFFu);
    float v = __fadd_rn(__fmul_rn(f, 2.0f), lo);
    v = fmaxf(lo, v);
    return __fmul_rn(__uint_as_float(0x3FB504F3u), erfinv_xla(v));
}

// ------------------------- degree / norm ------------------------------------
__global__ void k_deg_init(int n) {
    int i = blockIdx.x * blockDim.x + threadIdx.x;
    if (i < n) g_deg[i] = 1.0f;
}
__global__ void k_deg_count(const int* __restrict__ dst, int E) {
    int e = blockIdx.x * blockDim.x + threadIdx.x;
    if (e < E) atomicAdd(&g_deg[dst[e]], 1.0f);
}
__global__ void k_dinv(int n) {
    int i = blockIdx.x * blockDim.x + threadIdx.x;
    if (i < n) g_dinv[i] = (float)(1.0 / sqrt((double)g_deg[i]));
}
__global__ void k_self(int n4) {
    int idx = blockIdx.x * blockDim.x + threadIdx.x;
    if (idx >= n4) return;
    int node = idx >> 5;
    float di = g_dinv[node];
    float n2 = __fmul_rn(di, di);
    float4 v = ((const float4*)g_h)[idx];
    float4 o;
    o.x = __fmul_rn(v.x, n2); o.y = __fmul_rn(v.y, n2);
    o.z = __fmul_rn(v.z, n2); o.w = __fmul_rn(v.w, n2);
    ((float4*)g_agg)[idx] = o;
}
__global__ void k_scatter(const int* __restrict__ src, const int* __restrict__ dst, int E) {
    int e = blockIdx.x * 8 + (threadIdx.x >> 5);
    if (e >= E) return;
    int lane = threadIdx.x & 31;
    int s = __ldg(&src[e]);
    int d = __ldg(&dst[e]);
    float norm = __fmul_rn(g_dinv[s], g_dinv[d]);
    float4 v = *(const float4*)(g_h + (size_t)s * 128 + lane * 4);
    float* out = g_agg + (size_t)d * 128 + lane * 4;
    float m0 = __fmul_rn(v.x, norm);
    float m1 = __fmul_rn(v.y, norm);
    float m2 = __fmul_rn(v.z, norm);
    float m3 = __fmul_rn(v.w, norm);
    asm volatile("red.global.add.v4.f32 [%0], {%1,%2,%3,%4};"
                 :: "l"(out), "f"(m0), "f"(m1), "f"(m2), "f"(m3) : "memory");
}
__global__ void k_prep(const float* __restrict__ x, const float* __restrict__ bc, int n4) {
    int idx = blockIdx.x * blockDim.x + threadIdx.x;
    if (idx >= n4) return;
    int c4 = (idx & 31);
    float4 g = ((const float4*)g_agg)[idx];
    float4 xv = ((const float4*)x)[idx];
    float4 b = ((const float4*)bc)[c4];
    float4 o;
    o.x = __fadd_rn(fmaxf(__fadd_rn(g.x, b.x), 0.f), xv.x);
    o.y = __fadd_rn(fmaxf(__fadd_rn(g.y, b.y), 0.f), xv.y);
    o.z = __fadd_rn(fmaxf(__fadd_rn(g.z, b.z), 0.f), xv.z);
    o.w = __fadd_rn(fmaxf(__fadd_rn(g.w, b.w), 0.f), xv.w);
    ((float4*)g_h)[idx] = o;
}

// ------------------------- GEMM: double-buffered SGEMM ----------------------
// 128x128 block tile, 256 threads, 8x8 thread tile (split 4+4 cols), KB=8.
// Smem double-buffered + REGISTER fragment double-buffering (load frag k+1
// while computing frag k) so the FFMA stream never waits on LDS latency.
// EPI=0: C = A@W.  EPI=1: C = leaky(A@W + bout).
#define KB 8
#define PA 132

template<int K, int LDW, int LDA, int LDC, int EPI>
__global__ void __launch_bounds__(256, 2) k_gemm(const float* __restrict__ A,
                                                 const float* __restrict__ W,
                                                 const float* __restrict__ bout,
                                                 float* __restrict__ Cout, int N) {
    __shared__ float sA[2][KB][PA];
    __shared__ float sW[2][KB][128];

    const int t    = threadIdx.x;
    const int row0 = blockIdx.x * 128;
    const int c0   = blockIdx.y * 128;
    const int S    = K / KB;

    const int ar   = t >> 1;
    const int ak4  = (t & 1) * 4;
    const int wr   = t >> 5;
    const int wc4  = (t & 31) * 4;
    const int arow = row0 + ar;
    const bool aok = arow < N;

    const int tx = t & 15;
    const int ty = t >> 4;
    const int cx = tx * 4;          // cols cx..cx+3 and cx+64..cx+67
    const int r0 = ty * 8;

    float acc[8][8];
#pragma unroll
    for (int j = 0; j < 8; j++)
#pragma unroll
        for (int q = 0; q < 8; q++) acc[j][q] = 0.f;

    const float* Aptr = A + (size_t)arow * LDA + ak4;
    const float* Wptr = W + (size_t)wr * LDW + c0 + wc4;

    float4 va = make_float4(0.f, 0.f, 0.f, 0.f);
    if (aok) va = *(const float4*)(Aptr);
    float4 vw = *(const float4*)(Wptr);

    sA[0][ak4 + 0][ar] = va.x;
    sA[0][ak4 + 1][ar] = va.y;
    sA[0][ak4 + 2][ar] = va.z;
    sA[0][ak4 + 3][ar] = va.w;
    *(float4*)&sW[0][wr][wc4] = vw;
    __syncthreads();

    for (int s = 0; s < S; s++) {
        const int buf = s & 1;
        if (s + 1 < S) {
            int kc = (s + 1) * KB;
            if (aok) va = *(const float4*)(Aptr + kc);
            vw = *(const float4*)(Wptr + (size_t)kc * LDW);
        }

        // register-pipelined fragments: preload k=0
        float4 a0 = *(const float4*)&sA[buf][0][r0];
        float4 a1 = *(const float4*)&sA[buf][0][r0 + 4];
        float4 w0 = *(const float4*)&sW[buf][0][cx];
        float4 w1 = *(const float4*)&sW[buf][0][cx + 64];
#pragma unroll
        for (int k = 0; k < KB; k++) {
            float4 na0, na1, nw0, nw1;
            if (k + 1 < KB) {
                na0 = *(const float4*)&sA[buf][k + 1][r0];
                na1 = *(const float4*)&sA[buf][k + 1][r0 + 4];
                nw0 = *(const float4*)&sW[buf][k + 1][cx];
                nw1 = *(const float4*)&sW[buf][k + 1][cx + 64];
            }
#pragma unroll
            for (int j = 0; j < 8; j++) {
                float av = (j < 4) ? ((j == 0) ? a0.x : (j == 1) ? a0.y : (j == 2) ? a0.z : a0.w)
                                   : ((j == 4) ? a1.x : (j == 5) ? a1.y : (j == 6) ? a1.z : a1.w);
                acc[j][0] = fmaf(av, w0.x, acc[j][0]);
                acc[j][1] = fmaf(av, w0.y, acc[j][1]);
                acc[j][2] = fmaf(av, w0.z, acc[j][2]);
                acc[j][3] = fmaf(av, w0.w, acc[j][3]);
                acc[j][4] = fmaf(av, w1.x, acc[j][4]);
                acc[j][5] = fmaf(av, w1.y, acc[j][5]);
                acc[j][6] = fmaf(av, w1.z, acc[j][6]);
                acc[j][7] = fmaf(av, w1.w, acc[j][7]);
            }
            if (k + 1 < KB) { a0 = na0; a1 = na1; w0 = nw0; w1 = nw1; }
        }

        if (s + 1 < S) {
            const int nb = buf ^ 1;
            sA[nb][ak4 + 0][ar] = va.x;
            sA[nb][ak4 + 1][ar] = va.y;
            sA[nb][ak4 + 2][ar] = va.z;
            sA[nb][ak4 + 3][ar] = va.w;
            *(float4*)&sW[nb][wr][wc4] = vw;
        }
        __syncthreads();
    }

    float4 b0 = make_float4(0.f, 0.f, 0.f, 0.f);
    float4 b1v = b0;
    if (EPI) {
        b0  = *(const float4*)(bout + c0 + cx);
        b1v = *(const float4*)(bout + c0 + cx + 64);
    }
#pragma unroll
    for (int j = 0; j < 8; j++) {
        int row = row0 + r0 + j;
        if (row >= N) continue;
        float4 o0 = make_float4(acc[j][0], acc[j][1], acc[j][2], acc[j][3]);
        float4 o1 = make_float4(acc[j][4], acc[j][5], acc[j][6], acc[j][7]);
        if (EPI) {
            o0.x = __fadd_rn(o0.x, b0.x);  o0.x = (o0.x >= 0.f) ? o0.x : __fmul_rn(0.01f, o0.x);
            o0.y = __fadd_rn(o0.y, b0.y);  o0.y = (o0.y >= 0.f) ? o0.y : __fmul_rn(0.01f, o0.y);
            o0.z = __fadd_rn(o0.z, b0.z);  o0.z = (o0.z >= 0.f) ? o0.z : __fmul_rn(0.01f, o0.z);
            o0.w = __fadd_rn(o0.w, b0.w);  o0.w = (o0.w >= 0.f) ? o0.w : __fmul_rn(0.01f, o0.w);
            o1.x = __fadd_rn(o1.x, b1v.x); o1.x = (o1.x >= 0.f) ? o1.x : __fmul_rn(0.01f, o1.x);
            o1.y = __fadd_rn(o1.y, b1v.y); o1.y = (o1.y >= 0.f) ? o1.y : __fmul_rn(0.01f, o1.y);
            o1.z = __fadd_rn(o1.z, b1v.z); o1.z = (o1.z >= 0.f) ? o1.z : __fmul_rn(0.01f, o1.z);
            o1.w = __fadd_rn(o1.w, b1v.w); o1.w = (o1.w >= 0.f) ? o1.w : __fmul_rn(0.01f, o1.w);
        }
        *(float4*)(Cout + (size_t)row * LDC + c0 + cx)      = o0;
        *(float4*)(Cout + (size_t)row * LDC + c0 + cx + 64) = o1;
    }
}

// conc = softplus(h2 @ W3 + b3) + 1e-20   (warp per row)
__global__ void k_conc(const float* __restrict__ W3, const float* __restrict__ b3, int N) {
    int row = blockIdx.x * 8 + (threadIdx.x >> 5);
    if (row >= N) return;
    int lane = threadIdx.x & 31;
    const float4* hr = (const float4*)(g_h2 + (size_t)row * 256);
    const float4* w4 = (const float4*)W3;
    float s = 0.f;
#pragma unroll
    for (int j = lane; j < 64; j += 32) {
        float4 a = hr[j], w = w4[j];
        s = fmaf(a.x, w.x, s); s = fmaf(a.y, w.y, s);
        s = fmaf(a.z, w.z, s); s = fmaf(a.w, w.w, s);
    }
#pragma unroll
    for (int o = 16; o; o >>= 1) s += __shfl_xor_sync(0xFFFFFFFFu, s, o);
    if (lane == 0) {
        float z = __fadd_rn(s, b3[0]);
        double sp = fmax((double)z, 0.0) + log1p(exp(-fabs((double)z)));
        g_conc[row] = __fadd_rn((float)sp, 1e-20f);
    }
}

// ------------------------- loggamma sampler (jax _gamma_one) -----------------
__global__ void k_sample(int N) {
    int i = blockIdx.x * blockDim.x + threadIdx.x;
    if (i >= N) return;
    float alpha = g_conc[i];
    K2 key = split_big(K2{0u, 42u}, (unsigned)i);

    bool boost = (alpha >= 1.0f);
    float alpha_b = boost ? alpha : __fadd_rn(alpha, 1.0f);
    const float third = 0.3333333433f;
    float d = __fsub_rn(alpha_b, third);
    float c = __fdiv_rn(third, __fsqrt_rn(d));

    K2 k0, sub;
    split2(key, k0, sub);
    key = k0;
    float u_boost = u01(sub);

    float V;
    for (;;) {
        K2 nk, xk, uk;
        split3(key, nk, xk, uk);
        key = nk;
        float x, v;
        K2 kk = xk;
        do {
            K2 a, b;
            split2(kk, a, b);
            kk = a;
            x = nrm(b);
            v = __fadd_rn(1.0f, __fmul_rn(c, x));
        } while (v <= 0.0f);
        float X = __fmul_rn(x, x);
        V = __fmul_rn(__fmul_rn(v, v), v);
        float U = u01(uk);
        float sq = __fsub_rn(1.0f, __fmul_rn(0.0331f, __fmul_rn(X, X)));
        if (U < sq) break;
        float logU = (float)log((double)U);
        float logV = (float)log((double)V);
        float rhs = __fadd_rn(__fmul_rn(X, 0.5f),
                              __fmul_rn(d, __fadd_rn(__fsub_rn(1.0f, V), logV)));
        if (logU < rhs) break;
    }
    float log_sample = __fadd_rn((float)log((double)d), (float)log((double)V));
    float lg;
    if (boost) lg = log_sample;
    else {
        float lb = __fmul_rn((float)log1p(-(double)u_boost), __fdiv_rn(1.0f, alpha));
        lg = __fadd_rn(log_sample, lb);
    }
    g_lg[i] = lg;
}

// ------------------------- per-row finish: softmax + log_prob ----------------
__global__ void k_row(float* __restrict__ out, int N, int writeLP) {
    int b = blockIdx.x;
    int t = threadIdx.x;
    __shared__ float  rf[256];
    __shared__ double rd[256];
    const float* lg = g_lg   + (size_t)b * ADIM;
    const float* cc = g_conc + (size_t)b * ADIM;

    float m = -1e30f;
    for (int j = t; j < ADIM; j += 256) m = fmaxf(m, lg[j]);
    rf[t] = m; __syncthreads();
    for (int s = 128; s; s >>= 1) { if (t < s) rf[t] = fmaxf(rf[t], rf[t + s]); __syncthreads(); }
    m = rf[0]; __syncthreads();

    float se = 0.f;
    for (int j = t; j < ADIM; j += 256)
        se = __fadd_rn(se, (float)exp((double)__fsub_rn(lg[j], m)));
    rf[t] = se; __syncthreads();
    for (int s = 128; s; s >>= 1) { if (t < s) rf[t] = __fadd_rn(rf[t], rf[t + s]); __syncthreads(); }
    float lse = __fadd_rn((float)log((double)rf[0]), m);
    __syncthreads();

    double t1 = 0.0, t3 = 0.0, sc = 0.0;
    for (int j = t; j < ADIM; j += 256) {
        float af = (float)exp((double)__fsub_rn(lg[j], lse));
        out[(size_t)b * ADIM + j] = af;
        float cj = cc[j];
        t1 += (double)__fsub_rn(cj, 1.0f) * log((double)af);
        t3 += (double)lgammaf(cj);
        sc += (double)cj;
    }
    rd[t] = t1; __syncthreads();
    for (int s = 128; s; s >>= 1) { if (t < s) rd[t] += rd[t + s]; __syncthreads(); }
    t1 = rd[0]; __syncthreads();
    rd[t] = t3; __syncthreads();
    for (int s = 128; s; s >>= 1) { if (t < s) rd[t] += rd[t + s]; __syncthreads(); }
    t3 = rd[0]; __syncthreads();
    rd[t] = sc; __syncthreads();
    for (int s = 128; s; s >>= 1) { if (t < s) rd[t] += rd[t + s]; __syncthreads(); }
    sc = rd[0];

    if (t == 0 && writeLP) {
        float scf = (float)sc;
        double lp = t1 + lgamma((double)scf) - t3;
        out[(size_t)N + b] = (float)lp;
    }
}

// ------------------------- launch -------------------------------------------
extern "C" void kernel_launch(void* const* d_in, const int* in_sizes, int n_in,
                              void* d_out, int out_size) {
    const float* x      = (const float*)d_in[0];
    const float* W_conv = (const float*)d_in[1];
    const float* b_conv = (const float*)d_in[2];
    const float* W1     = (const float*)d_in[3];
    const float* b1     = (const float*)d_in[4];
    const float* W2     = (const float*)d_in[5];
    const float* b2     = (const float*)d_in[6];
    const float* W3     = (const float*)d_in[7];
    const float* b3     = (const float*)d_in[8];
    const int*   ei     = (const int*)d_in[9];
    float* out = (float*)d_out;

    int N = in_sizes[0] / 128;
    int E = in_sizes[9] / 2;
    int B = N / ADIM;
    const int* src = ei;
    const int* dst = ei + E;

    k_deg_init<<<(N + 255) / 256, 256>>>(N);
    k_deg_count<<<(E + 255) / 256, 256>>>(dst, E);
    k_dinv<<<(N + 255) / 256, 256>>>(N);

    float* gh = nullptr; float* gh1 = nullptr; float* gh2 = nullptr;
    cudaGetSymbolAddress((void**)&gh,  g_h);
    cudaGetSymbolAddress((void**)&gh1, g_h1);
    cudaGetSymbolAddress((void**)&gh2, g_h2);

    int RB = (N + 127) / 128;
    dim3 g0(RB, 1), g1(RB, 2);

    // h = x @ Wc
    k_gemm<128,128,128,128,0><<<g0, 256>>>(x, W_conv, nullptr, gh, N);
    k_self<<<(N * 32 + 255) / 256, 256>>>(N * 32);
    k_scatter<<<(E + 7) / 8, 256>>>(src, dst, E);
    // g_h <- relu(agg + b_conv) + x
    k_prep<<<(N * 32 + 255) / 256, 256>>>(x, b_conv, N * 32);
    // h1 = leaky(g_h @ W1 + b1)
    k_gemm<128,256,128,256,1><<<g1, 256>>>(gh, W1, b1, gh1, N);
    // h2 = leaky(h1 @ W2 + b2)
    k_gemm<256,256,256,256,1><<<g1, 256>>>(gh1, W2, b2, gh2, N);
    k_conc<<<(N + 7) / 8, 256>>>(W3, b3, N);
    k_sample<<<(N + 127) / 128, 128>>>(N);
    int writeLP = (out_size >= N + B) ? 1 : 0;
    k_row<<<B, 256>>>(out, N, writeLP);
}

// round 10
// speedup vs baseline: 1.2074x; 1.1278x over previous
#include <cuda_runtime.h>
#include <math.h>
#include <stdint.h>

#define NN_MAX 100000
#define ADIM   1000

// ------------------------- scratch (no runtime alloc) -----------------------
__device__ float g_h   [(size_t)NN_MAX*128];
__device__ float g_agg [(size_t)NN_MAX*128];
__device__ float g_h1  [(size_t)NN_MAX*256];
__device__ float g_h2  [(size_t)NN_MAX*256];
__device__ float g_deg [NN_MAX];
__device__ float g_dinv[NN_MAX];
__device__ float g_conc[NN_MAX];
__device__ float g_lg  [NN_MAX];

// ------------------------- threefry2x32 (JAX-exact) -------------------------
struct K2 { unsigned a, b; };

__device__ __forceinline__ void tf_round(unsigned &x0, unsigned &x1, int r) {
    x0 += x1;
    x1 = (x1 << r) | (x1 >> (32 - r));
    x1 ^= x0;
}
__device__ __forceinline__ K2 tf_block(unsigned k0, unsigned k1, unsigned x0, unsigned x1) {
    unsigned k2 = k0 ^ k1 ^ 0x1BD11BDAu;
    x0 += k0; x1 += k1;
    tf_round(x0,x1,13); tf_round(x0,x1,15); tf_round(x0,x1,26); tf_round(x0,x1,6);
    x0 += k1; x1 += k2 + 1u;
    tf_round(x0,x1,17); tf_round(x0,x1,29); tf_round(x0,x1,16); tf_round(x0,x1,24);
    x0 += k2; x1 += k0 + 2u;
    tf_round(x0,x1,13); tf_round(x0,x1,15); tf_round(x0,x1,26); tf_round(x0,x1,6);
    x0 += k0; x1 += k1 + 3u;
    tf_round(x0,x1,17); tf_round(x0,x1,29); tf_round(x0,x1,16); tf_round(x0,x1,24);
    x0 += k1; x1 += k2 + 4u;
    tf_round(x0,x1,13); tf_round(x0,x1,15); tf_round(x0,x1,26); tf_round(x0,x1,6);
    x0 += k2; x1 += k0 + 5u;
    K2 r; r.a = x0; r.b = x1; return r;
}
__device__ __forceinline__ unsigned rbits(K2 k) {
    K2 r = tf_block(k.a, k.b, 0u, 0u);
    return r.a ^ r.b;
}
__device__ __forceinline__ void split2(K2 k, K2 &o0, K2 &o1) {
    o0 = tf_block(k.a, k.b, 0u, 0u);
    o1 = tf_block(k.a, k.b, 0u, 1u);
}
__device__ __forceinline__ void split3(K2 k, K2 &o0, K2 &o1, K2 &o2) {
    o0 = tf_block(k.a, k.b, 0u, 0u);
    o1 = tf_block(k.a, k.b, 0u, 1u);
    o2 = tf_block(k.a, k.b, 0u, 2u);
}
__device__ __forceinline__ K2 split_big(K2 k, unsigned i) {
    return tf_block(k.a, k.b, 0u, i);
}
__device__ __forceinline__ float u01(K2 k) {
    unsigned bits = rbits(k);
    return __uint_as_float((bits >> 9) | 0x3f800000u) - 1.0f;
}
__device__ __forceinline__ float erfinv_xla(float x) {
    float xx = __fmul_rn(x, x);
    float w = (float)(-log1p(-(double)xx));
    float p;
    if (w < 5.0f) {
        w = __fsub_rn(w, 2.5f);
        p = 2.81022636e-08f;
        p = fmaf(p, w, 3.43273939e-07f);
        p = fmaf(p, w, -3.5233877e-06f);
        p = fmaf(p, w, -4.39150654e-06f);
        p = fmaf(p, w, 0.00021858087f);
        p = fmaf(p, w, -0.00125372503f);
        p = fmaf(p, w, -0.00417768164f);
        p = fmaf(p, w, 0.246640727f);
        p = fmaf(p, w, 1.50140941f);
    } else {
        w = __fsub_rn(__fsqrt_rn(w), 3.0f);
        p = -0.000200214257f;
        p = fmaf(p, w, 0.000100950558f);
        p = fmaf(p, w, 0.00134934322f);
        p = fmaf(p, w, -0.00367342844f);
        p = fmaf(p, w, 0.00573950773f);
        p = fmaf(p, w, -0.0076224613f);
        p = fmaf(p, w, 0.00943887047f);
        p = fmaf(p, w, 1.00167406f);
        p = fmaf(p, w, 2.83297682f);
    }
    return __fmul_rn(p, x);
}
__device__ __forceinline__ float nrm(K2 k) {
    float f = u01(k);
    const float lo = __uint_as_float(0xBF7FFFFFu);
    float v = __fadd_rn(__fmul_rn(f, 2.0f), lo);
    v = fmaxf(lo, v);
    return __fmul_rn(__uint_as_float(0x3FB504F3u), erfinv_xla(v));
}

// ------------------------- degree / norm ------------------------------------
__global__ void k_deg_init(int n) {
    int i = blockIdx.x * blockDim.x + threadIdx.x;
    if (i < n) g_deg[i] = 1.0f;
}
__global__ void k_deg_count(const int* __restrict__ dst, int E) {
    int e = blockIdx.x * blockDim.x + threadIdx.x;
    if (e < E) atomicAdd(&g_deg[dst[e]], 1.0f);
}
__global__ void k_dinv(int n) {
    int i = blockIdx.x * blockDim.x + threadIdx.x;
    if (i < n) g_dinv[i] = (float)(1.0 / sqrt((double)g_deg[i]));
}
__global__ void k_self(int n4) {
    int idx = blockIdx.x * blockDim.x + threadIdx.x;
    if (idx >= n4) return;
    int node = idx >> 5;
    float di = g_dinv[node];
    float n2 = __fmul_rn(di, di);
    float4 v = ((const float4*)g_h)[idx];
    float4 o;
    o.x = __fmul_rn(v.x, n2); o.y = __fmul_rn(v.y, n2);
    o.z = __fmul_rn(v.z, n2); o.w = __fmul_rn(v.w, n2);
    ((float4*)g_agg)[idx] = o;
}
__global__ void k_scatter(const int* __restrict__ src, const int* __restrict__ dst, int E) {
    int e = blockIdx.x * 8 + (threadIdx.x >> 5);
    if (e >= E) return;
    int lane = threadIdx.x & 31;
    int s = __ldg(&src[e]);
    int d = __ldg(&dst[e]);
    float norm = __fmul_rn(g_dinv[s], g_dinv[d]);
    float4 v = *(const float4*)(g_h + (size_t)s * 128 + lane * 4);
    float* out = g_agg + (size_t)d * 128 + lane * 4;
    float m0 = __fmul_rn(v.x, norm);
    float m1 = __fmul_rn(v.y, norm);
    float m2 = __fmul_rn(v.z, norm);
    float m3 = __fmul_rn(v.w, norm);
    asm volatile("red.global.add.v4.f32 [%0], {%1,%2,%3,%4};"
                 :: "l"(out), "f"(m0), "f"(m1), "f"(m2), "f"(m3) : "memory");
}
__global__ void k_prep(const float* __restrict__ x, const float* __restrict__ bc, int n4) {
    int idx = blockIdx.x * blockDim.x + threadIdx.x;
    if (idx >= n4) return;
    int c4 = (idx & 31);
    float4 g = ((const float4*)g_agg)[idx];
    float4 xv = ((const float4*)x)[idx];
    float4 b = ((const float4*)bc)[c4];
    float4 o;
    o.x = __fadd_rn(fmaxf(__fadd_rn(g.x, b.x), 0.f), xv.x);
    o.y = __fadd_rn(fmaxf(__fadd_rn(g.y, b.y), 0.f), xv.y);
    o.z = __fadd_rn(fmaxf(__fadd_rn(g.z, b.z), 0.f), xv.z);
    o.w = __fadd_rn(fmaxf(__fadd_rn(g.w, b.w), 0.f), xv.w);
    ((float4*)g_h)[idx] = o;
}

// ------------------------- 3xTF32 mma.sync GEMM -----------------------------
// C = A @ W with fp32-class accuracy on the tensor pipe (legacy HMMA path):
// x = hi + lo (tf32 each); acc += hi*hi + hi*lo + lo*hi  (fp32 accum).
// CTA: 128x128, 8 warps (warp tile 32M x 64N = 2x8 m16n8k8 tiles), K-slice 8.
// Smem: k-major, stride 136 (mod 32 == 8) => conflict-free fragment loads.
// EPI=0: C = A@W.  EPI=1: C = leaky(A@W + bout).
#define PS 136

__device__ __forceinline__ uint32_t f2tf(float x) {
    uint32_t r;
    asm("cvt.rna.tf32.f32 %0, %1;" : "=r"(r) : "f"(x));
    return r;
}

#define MMA_TF32(c, a, b0, b1) \
    asm volatile("mma.sync.aligned.m16n8k8.row.col.f32.tf32.tf32.f32 " \
                 "{%0,%1,%2,%3}, {%4,%5,%6,%7}, {%8,%9}, {%0,%1,%2,%3};" \
                 : "+f"((c)[0]), "+f"((c)[1]), "+f"((c)[2]), "+f"((c)[3]) \
                 : "r"((a)[0]), "r"((a)[1]), "r"((a)[2]), "r"((a)[3]), \
                   "r"(b0), "r"(b1))

template<int K, int LDW, int LDA, int LDC, int EPI>
__global__ void __launch_bounds__(256, 2) k_gemm(const float* __restrict__ A,
                                                 const float* __restrict__ W,
                                                 const float* __restrict__ bout,
                                                 float* __restrict__ Cout, int N) {
    __shared__ uint32_t sAh[2][8][PS];
    __shared__ uint32_t sAl[2][8][PS];
    __shared__ uint32_t sWh[2][8][PS];
    __shared__ uint32_t sWl[2][8][PS];

    const int t    = threadIdx.x;
    const int row0 = blockIdx.x * 128;
    const int c0   = blockIdx.y * 128;
    const int S    = K / 8;

    // loader indices
    const int lr   = t >> 1;               // A row 0..127
    const int lk4  = (t & 1) * 4;          // A k-offset 0/4
    const int wk   = t >> 5;               // W k-row 0..7
    const int wc4  = (t & 31) * 4;         // W col
    const bool aok = (row0 + lr) < N;
    const float* Ap = A + (size_t)(row0 + lr) * LDA + lk4;
    const float* Wp = W + (size_t)wk * LDW + c0 + wc4;

    // compute indices
    const int lane = t & 31;
    const int g    = lane >> 2;
    const int tig  = lane & 3;
    const int wid  = t >> 5;
    const int wm   = wid & 3;              // 4 warps along M
    const int wn   = wid >> 2;             // 2 warps along N
    const int rowb = wm * 32;
    const int colb = wn * 64;

    float acc[2][8][4];
#pragma unroll
    for (int m = 0; m < 2; m++)
#pragma unroll
        for (int n = 0; n < 8; n++)
#pragma unroll
            for (int q = 0; q < 4; q++) acc[m][n][q] = 0.f;

    float4 va = make_float4(0.f, 0.f, 0.f, 0.f), vw;
    if (aok) va = *(const float4*)(Ap);
    vw = *(const float4*)(Wp);

    // split+store registers -> smem buffer b
    auto sstore = [&](int b) {
        const float* vaf = (const float*)&va;
        const float* vwf = (const float*)&vw;
#pragma unroll
        for (int j = 0; j < 4; j++) {
            float x = vaf[j];
            uint32_t hi = f2tf(x);
            uint32_t lo = f2tf(__fsub_rn(x, __uint_as_float(hi)));
            sAh[b][lk4 + j][lr] = hi;
            sAl[b][lk4 + j][lr] = lo;
            float y = vwf[j];
            uint32_t hw = f2tf(y);
            uint32_t lw = f2tf(__fsub_rn(y, __uint_as_float(hw)));
            sWh[b][wk][wc4 + j] = hw;
            sWl[b][wk][wc4 + j] = lw;
        }
    };

    sstore(0);
    __syncthreads();

    for (int s = 0; s < S; s++) {
        const int buf = s & 1;
        if (s + 1 < S) {
            int kc = (s + 1) * 8;
            if (aok) va = *(const float4*)(Ap + kc);
            vw = *(const float4*)(Wp + (size_t)kc * LDW);
        }

        // A fragments (hi+lo), conflict-free (stride 136)
        uint32_t ah[2][4], al[2][4];
#pragma unroll
        for (int m = 0; m < 2; m++) {
            int rb = rowb + m * 16 + g;
            ah[m][0] = sAh[buf][tig    ][rb];
            ah[m][1] = sAh[buf][tig    ][rb + 8];
            ah[m][2] = sAh[buf][tig + 4][rb];
            ah[m][3] = sAh[buf][tig + 4][rb + 8];
            al[m][0] = sAl[buf][tig    ][rb];
            al[m][1] = sAl[buf][tig    ][rb + 8];
            al[m][2] = sAl[buf][tig + 4][rb];
            al[m][3] = sAl[buf][tig + 4][rb + 8];
        }
#pragma unroll
        for (int n = 0; n < 8; n++) {
            int col = colb + n * 8 + g;
            uint32_t bh0 = sWh[buf][tig    ][col];
            uint32_t bh1 = sWh[buf][tig + 4][col];
            uint32_t bl0 = sWl[buf][tig    ][col];
            uint32_t bl1 = sWl[buf][tig + 4][col];
#pragma unroll
            for (int m = 0; m < 2; m++) {
                MMA_TF32(acc[m][n], ah[m], bh0, bh1);
                MMA_TF32(acc[m][n], ah[m], bl0, bl1);
                MMA_TF32(acc[m][n], al[m], bh0, bh1);
            }
        }

        if (s + 1 < S) sstore(buf ^ 1);
        __syncthreads();
    }

    // epilogue
#pragma unroll
    for (int m = 0; m < 2; m++) {
#pragma unroll
        for (int n = 0; n < 8; n++) {
            int rl  = row0 + rowb + m * 16 + g;
            int rh  = rl + 8;
            int col = c0 + colb + n * 8 + 2 * tig;
            float2 bv = make_float2(0.f, 0.f);
            if (EPI) bv = *(const float2*)(bout + col);
            float v0 = acc[m][n][0], v1 = acc[m][n][1];
            float v2 = acc[m][n][2], v3 = acc[m][n][3];
            if (EPI) {
                v0 = __fadd_rn(v0, bv.x); v0 = (v0 >= 0.f) ? v0 : __fmul_rn(0.01f, v0);
                v1 = __fadd_rn(v1, bv.y); v1 = (v1 >= 0.f) ? v1 : __fmul_rn(0.01f, v1);
                v2 = __fadd_rn(v2, bv.x); v2 = (v2 >= 0.f) ? v2 : __fmul_rn(0.01f, v2);
                v3 = __fadd_rn(v3, bv.y); v3 = (v3 >= 0.f) ? v3 : __fmul_rn(0.01f, v3);
            }
            if (rl < N) *(float2*)(Cout + (size_t)rl * LDC + col) = make_float2(v0, v1);
            if (rh < N) *(float2*)(Cout + (size_t)rh * LDC + col) = make_float2(v2, v3);
        }
    }
}

// conc = softplus(h2 @ W3 + b3) + 1e-20   (warp per row)
__global__ void k_conc(const float* __restrict__ W3, const float* __restrict__ b3, int N) {
    int row = blockIdx.x * 8 + (threadIdx.x >> 5);
    if (row >= N) return;
    int lane = threadIdx.x & 31;
    const float4* hr = (const float4*)(g_h2 + (size_t)row * 256);
    const float4* w4 = (const float4*)W3;
    float s = 0.f;
#pragma unroll
    for (int j = lane; j < 64; j += 32) {
        float4 a = hr[j], w = w4[j];
        s = fmaf(a.x, w.x, s); s = fmaf(a.y, w.y, s);
        s = fmaf(a.z, w.z, s); s = fmaf(a.w, w.w, s);
    }
#pragma unroll
    for (int o = 16; o; o >>= 1) s += __shfl_xor_sync(0xFFFFFFFFu, s, o);
    if (lane == 0) {
        float z = __fadd_rn(s, b3[0]);
        double sp = fmax((double)z, 0.0) + log1p(exp(-fabs((double)z)));
        g_conc[row] = __fadd_rn((float)sp, 1e-20f);
    }
}

// ------------------------- loggamma sampler (jax _gamma_one) -----------------
__global__ void k_sample(int N) {
    int i = blockIdx.x * blockDim.x + threadIdx.x;
    if (i >= N) return;
    float alpha = g_conc[i];
    K2 key = split_big(K2{0u, 42u}, (unsigned)i);

    bool boost = (alpha >= 1.0f);
    float alpha_b = boost ? alpha : __fadd_rn(alpha, 1.0f);
    const float third = 0.3333333433f;
    float d = __fsub_rn(alpha_b, third);
    float c = __fdiv_rn(third, __fsqrt_rn(d));

    K2 k0, sub;
    split2(key, k0, sub);
    key = k0;
    float u_boost = u01(sub);

    float V;
    for (;;) {
        K2 nk, xk, uk;
        split3(key, nk, xk, uk);
        key = nk;
        float x, v;
        K2 kk = xk;
        do {
            K2 a, b;
            split2(kk, a, b);
            kk = a;
            x = nrm(b);
            v = __fadd_rn(1.0f, __fmul_rn(c, x));
        } while (v <= 0.0f);
        float X = __fmul_rn(x, x);
        V = __fmul_rn(__fmul_rn(v, v), v);
        float U = u01(uk);
        float sq = __fsub_rn(1.0f, __fmul_rn(0.0331f, __fmul_rn(X, X)));
        if (U < sq) break;
        float logU = (float)log((double)U);
        float logV = (float)log((double)V);
        float rhs = __fadd_rn(__fmul_rn(X, 0.5f),
                              __fmul_rn(d, __fadd_rn(__fsub_rn(1.0f, V), logV)));
        if (logU < rhs) break;
    }
    float log_sample = __fadd_rn((float)log((double)d), (float)log((double)V));
    float lg;
    if (boost) lg = log_sample;
    else {
        float lb = __fmul_rn((float)log1p(-(double)u_boost), __fdiv_rn(1.0f, alpha));
        lg = __fadd_rn(log_sample, lb);
    }
    g_lg[i] = lg;
}

// ------------------------- per-row finish: softmax + log_prob ----------------
__global__ void k_row(float* __restrict__ out, int N, int writeLP) {
    int b = blockIdx.x;
    int t = threadIdx.x;
    __shared__ float  rf[256];
    __shared__ double rd[256];
    const float* lg = g_lg   + (size_t)b * ADIM;
    const float* cc = g_conc + (size_t)b * ADIM;

    float m = -1e30f;
    for (int j = t; j < ADIM; j += 256) m = fmaxf(m, lg[j]);
    rf[t] = m; __syncthreads();
    for (int s = 128; s; s >>= 1) { if (t < s) rf[t] = fmaxf(rf[t], rf[t + s]); __syncthreads(); }
    m = rf[0]; __syncthreads();

    float se = 0.f;
    for (int j = t; j < ADIM; j += 256)
        se = __fadd_rn(se, (float)exp((double)__fsub_rn(lg[j], m)));
    rf[t] = se; __syncthreads();
    for (int s = 128; s; s >>= 1) { if (t < s) rf[t] = __fadd_rn(rf[t], rf[t + s]); __syncthreads(); }
    float lse = __fadd_rn((float)log((double)rf[0]), m);
    __syncthreads();

    double t1 = 0.0, t3 = 0.0, sc = 0.0;
    for (int j = t; j < ADIM; j += 256) {
        float af = (float)exp((double)__fsub_rn(lg[j], lse));
        out[(size_t)b * ADIM + j] = af;
        float cj = cc[j];
        t1 += (double)__fsub_rn(cj, 1.0f) * log((double)af);
        t3 += (double)lgammaf(cj);
        sc += (double)cj;
    }
    rd[t] = t1; __syncthreads();
    for (int s = 128; s; s >>= 1) { if (t < s) rd[t] += rd[t + s]; __syncthreads(); }
    t1 = rd[0]; __syncthreads();
    rd[t] = t3; __syncthreads();
    for (int s = 128; s; s >>= 1) { if (t < s) rd[t] += rd[t + s]; __syncthreads(); }
    t3 = rd[0]; __syncthreads();
    rd[t] = sc; __syncthreads();
    for (int s = 128; s; s >>= 1) { if (t < s) rd[t] += rd[t + s]; __syncthreads(); }
    sc = rd[0];

    if (t == 0 && writeLP) {
        float scf = (float)sc;
        double lp = t1 + lgamma((double)scf) - t3;
        out[(size_t)N + b] = (float)lp;
    }
}

// ------------------------- launch -------------------------------------------
extern "C" void kernel_launch(void* const* d_in, const int* in_sizes, int n_in,
                              void* d_out, int out_size) {
    const float* x      = (const float*)d_in[0];
    const float* W_conv = (const float*)d_in[1];
    const float* b_conv = (const float*)d_in[2];
    const float* W1     = (const float*)d_in[3];
    const float* b1     = (const float*)d_in[4];
    const float* W2     = (const float*)d_in[5];
    const float* b2     = (const float*)d_in[6];
    const float* W3     = (const float*)d_in[7];
    const float* b3     = (const float*)d_in[8];
    const int*   ei     = (const int*)d_in[9];
    float* out = (float*)d_out;

    int N = in_sizes[0] / 128;
    int E = in_sizes[9] / 2;
    int B = N / ADIM;
    const int* src = ei;
    const int* dst = ei + E;

    k_deg_init<<<(N + 255) / 256, 256>>>(N);
    k_deg_count<<<(E + 255) / 256, 256>>>(dst, E);
    k_dinv<<<(N + 255) / 256, 256>>>(N);

    float* gh = nullptr; float* gh1 = nullptr; float* gh2 = nullptr;
    cudaGetSymbolAddress((void**)&gh,  g_h);
    cudaGetSymbolAddress((void**)&gh1, g_h1);
    cudaGetSymbolAddress((void**)&gh2, g_h2);

    int RB = (N + 127) / 128;
    dim3 g0(RB, 1), g1(RB, 2);

    // h = x @ Wc
    k_gemm<128,128,128,128,0><<<g0, 256>>>(x, W_conv, nullptr, gh, N);
    k_self<<<(N * 32 + 255) / 256, 256>>>(N * 32);
    k_scatter<<<(E + 7) / 8, 256>>>(src, dst, E);
    // g_h <- relu(agg + b_conv) + x
    k_prep<<<(N * 32 + 255) / 256, 256>>>(x, b_conv, N * 32);
    // h1 = leaky(g_h @ W1 + b1)
    k_gemm<128,256,128,256,1><<<g1, 256>>>(gh, W1, b1, gh1, N);
    // h2 = leaky(h1 @ W2 + b2)
    k_gemm<256,256,256,256,1><<<g1, 256>>>(gh1, W2, b2, gh2, N);
    k_conc<<<(N + 7) / 8, 256>>>(W3, b3, N);
    k_sample<<<(N + 127) / 128, 128>>>(N);
    int writeLP = (out_size >= N + B) ? 1 : 0;
    k_row<<<B, 256>>>(out, N, writeLP);
}